// round 4
// baseline (speedup 1.0000x reference)
#include <cuda_runtime.h>

#define DD   16
#define HH   56
#define WW   56
#define PP   (DD*HH*WW)      // 50176
#define CIN  32
#define COUT 64
#define KK   27
#define COFF 81
#define DHW  PP
#define OWPAD 84

// deform tiling: block = one z-plane slice, 4 consecutive y rows, all x.
#define NROW 4
#define TB   (NROW*WW)       // 224 threads
#define NYG  (HH/NROW)       // 14 y-groups
#define TZd  10              // z tile: zo-4 .. zo+5
#define TYd  13              // y tile: y0-4 .. y0+8
#define TXd  65              // x tile: -4 .. 60
#define ZLO  (-4)
#define YLO  (-4)
#define XLO  (-4)
#define CIPB 8               // ci per deform block
#define NCIG (CIN/CIPB)      // 4

__device__ float g_off[COFF * PP];
__device__ float g_wr [KK * CIN * COUT];
__device__ float g_owr[KK * CIN * OWPAD];

// ---- packed fp32x2 helpers ------------------------------------------------
__device__ __forceinline__ unsigned long long fma2(unsigned long long a,
                                                   unsigned long long b,
                                                   unsigned long long c) {
    unsigned long long d;
    asm("fma.rn.f32x2 %0, %1, %2, %3;" : "=l"(d) : "l"(a), "l"(b), "l"(c));
    return d;
}
__device__ __forceinline__ unsigned long long pack2(float s) {
    unsigned long long d;
    asm("mov.b64 %0, {%1, %1};" : "=l"(d) : "f"(s));
    return d;
}
__device__ __forceinline__ void unpack2(unsigned long long v, float& lo, float& hi) {
    asm("mov.b64 {%0, %1}, %2;" : "=f"(lo), "=f"(hi) : "l"(v));
}

// ---------------------------------------------------------------------------
// Init: rearrange weights + initialize out with bias (deform red.adds into it)
// ---------------------------------------------------------------------------
__global__ void init_kernel(const float* __restrict__ offw,
                            const float* __restrict__ w,
                            const float* __restrict__ bias,
                            float* __restrict__ out) {
    int i = blockIdx.x * blockDim.x + threadIdx.x;
    if (i < KK * CIN * OWPAD) {
        int c  = i % OWPAD;
        int t  = i / OWPAD;
        int ci = t % CIN;
        int k  = t / CIN;
        g_owr[i] = (c < COFF) ? offw[(c * CIN + ci) * KK + k] : 0.f;
    }
    if (i < KK * CIN * COUT) {
        int co = i % COUT;
        int t  = i / COUT;
        int ci = t % CIN;
        int k  = t / CIN;
        g_wr[i] = w[(co * CIN + ci) * KK + k];
    }
    if (i < COUT * PP) {
        out[i] = __ldg(bias + i / PP);
    }
}

// ---------------------------------------------------------------------------
// Stage 1: dense offset conv (near its fp32 FLOP floor)
// ---------------------------------------------------------------------------
__global__ __launch_bounds__(128)
void offconv_kernel(const float* __restrict__ x, const float* __restrict__ ob) {
    __shared__ __align__(16) float ws[CIN * OWPAD];

    int tid   = threadIdx.x;
    int gwarp = blockIdx.x * 4 + (tid >> 5);
    int lane  = tid & 31;
    int p     = gwarp * 32 + lane;
    int zo    = p / (HH * WW);
    int r     = p - zo * (HH * WW);
    int yo    = r / WW;
    int xo    = r - yo * WW;

    unsigned long long acc2[OWPAD / 2];
#pragma unroll
    for (int c = 0; c < OWPAD / 2; c++) acc2[c] = 0ull;

#pragma unroll 1
    for (int k = 0; k < KK; k++) {
        __syncthreads();
        {
            const float4* src = (const float4*)(g_owr + k * CIN * OWPAD);
            float4* dst = (float4*)ws;
            for (int i = tid; i < (CIN * OWPAD) / 4; i += 128) dst[i] = src[i];
        }
        __syncthreads();

        int kz = k / 9, ky = (k / 3) % 3, kx = k % 3;
        int zi = zo + kz - 1, yi = yo + ky - 1, xi = xo + kx - 1;
        bool valid = ((unsigned)zi < DD) & ((unsigned)yi < HH) & ((unsigned)xi < WW);
        int xidx = (zi * HH + yi) * WW + xi;

#pragma unroll 4
        for (int ci = 0; ci < CIN; ci++) {
            float xv = valid ? __ldg(x + ci * DHW + xidx) : 0.f;
            unsigned long long xv2 = pack2(xv);
            const ulonglong2* wv = (const ulonglong2*)(ws + ci * OWPAD);
#pragma unroll
            for (int j = 0; j < OWPAD / 4; j++) {
                ulonglong2 w2 = wv[j];
                acc2[2*j+0] = fma2(xv2, w2.x, acc2[2*j+0]);
                acc2[2*j+1] = fma2(xv2, w2.y, acc2[2*j+1]);
            }
        }
    }

#pragma unroll
    for (int i = 0; i < OWPAD / 2; i++) {
        float lo, hi;
        unpack2(acc2[i], lo, hi);
        int c = 2 * i;
        if (c < COFF)     g_off[c * PP + p]       = lo + __ldg(ob + c);
        if (c + 1 < COFF) g_off[(c + 1) * PP + p] = hi + __ldg(ob + c + 1);
    }
}

// ---------------------------------------------------------------------------
// Stage 2: deformable sampling with smem-tiled x (gathers via LDS, not LDG).
// Grid: (224 regions) x (4 ci-groups). red.add into bias-initialized out.
// ---------------------------------------------------------------------------
__global__ __launch_bounds__(TB)
void deform_kernel(const float* __restrict__ x, float* __restrict__ out) {
    __shared__ __align__(16) float xt[TZd * TYd * TXd];  // 33.8 KB
    __shared__ __align__(16) float wsl[KK * COUT];       //  6.9 KB

    int t   = threadIdx.x;
    int reg = blockIdx.x;            // 0..223
    int zo  = reg / NYG;
    int y0  = (reg % NYG) * NROW;
    int cig = blockIdx.y;            // 0..3
    int yo  = y0 + t / WW;
    int xo  = t % WW;
    int p   = (zo * HH + yo) * WW + xo;

    unsigned long long acc2[COUT / 2];
#pragma unroll
    for (int i = 0; i < COUT / 2; i++) acc2[i] = 0ull;

#pragma unroll 1
    for (int cc = 0; cc < CIPB; cc++) {
        int ci = cig * CIPB + cc;
        __syncthreads();   // protect previous tile from overwrite

        // stage x tile (zero-filled outside volume -> zero-pad semantics)
        const float* xc = x + ci * DHW;
        for (int i = t; i < TZd * TYd * TXd; i += TB) {
            int r  = i / TXd;
            int c  = i - r * TXd;
            int zr = r / TYd;
            int yr = r - zr * TYd;
            int zi = zo + ZLO + zr;
            int yi = y0 + YLO + yr;
            int xi = XLO + c;
            float v = 0.f;
            if (((unsigned)zi < DD) & ((unsigned)yi < HH) & ((unsigned)xi < WW))
                v = __ldg(xc + (zi * HH + yi) * WW + xi);
            xt[i] = v;
        }
        // stage weight slice [k][co] for this ci
        for (int i = t; i < KK * COUT; i += TB) {
            int k  = i >> 6;
            int co = i & 63;
            wsl[i] = g_wr[(k * CIN + ci) * COUT + co];
        }
        __syncthreads();

#pragma unroll 1
        for (int k = 0; k < KK; k++) {
            int kz = k / 9, ky = (k / 3) % 3, kx = k % 3;
            float dz = __ldg(g_off + (3*k+0) * PP + p);
            float dy = __ldg(g_off + (3*k+1) * PP + p);
            float dx = __ldg(g_off + (3*k+2) * PP + p);
            float zc = (float)(zo + kz - 1) + dz;
            float yc = (float)(yo + ky - 1) + dy;
            float xc2= (float)(xo + kx - 1) + dx;
            float zf = floorf(zc), yf = floorf(yc), xf = floorf(xc2);
            float fz = zc - zf, fy = yc - yf, fx = xc2 - xf;
            int z0 = (int)zf, y0i = (int)yf, x0 = (int)xf;
            // tile-relative corner base
            int tz = z0 - (zo + ZLO);
            int ty = y0i - (y0 + YLO);
            int tx = x0 - XLO;

            float w8[8], v8[8];
            unsigned esc = 0u;
#pragma unroll
            for (int j = 0; j < 8; j++) {
                int dzc = (j >> 2) & 1, dyc = (j >> 1) & 1, dxc = j & 1;
                int az = tz + dzc, ay = ty + dyc, ax = tx + dxc;
                bool in = ((unsigned)az < TZd) & ((unsigned)ay < TYd) & ((unsigned)ax < TXd);
                esc |= ((unsigned)(!in)) << j;
                int sidx = in ? (az * TYd + ay) * TXd + ax : 0;
                v8[j] = xt[sidx];
                float wz = dzc ? fz : 1.f - fz;
                float wy = dyc ? fy : 1.f - fy;
                float wx = dxc ? fx : 1.f - fx;
                w8[j] = wz * wy * wx;
            }
            // tile escape (P ~ 2e-7 per corner): exact global fallback
            if (__any_sync(0xffffffffu, esc != 0u)) {
#pragma unroll
                for (int j = 0; j < 8; j++) if (esc & (1u << j)) {
                    int dzc = (j >> 2) & 1, dyc = (j >> 1) & 1, dxc = j & 1;
                    int zi = z0 + dzc, yi = y0i + dyc, xi = x0 + dxc;
                    bool vin = ((unsigned)zi < DD) & ((unsigned)yi < HH) & ((unsigned)xi < WW);
                    v8[j] = vin ? __ldg(x + ci * DHW + (zi * HH + yi) * WW + xi) : 0.f;
                }
            }
            float s = 0.f;
#pragma unroll
            for (int j = 0; j < 8; j++) s += w8[j] * v8[j];

            unsigned long long s2 = pack2(s);
            const ulonglong2* wv = (const ulonglong2*)(wsl + k * COUT);
#pragma unroll
            for (int j = 0; j < COUT / 4; j++) {
                ulonglong2 w2 = wv[j];
                acc2[2*j+0] = fma2(s2, w2.x, acc2[2*j+0]);
                acc2[2*j+1] = fma2(s2, w2.y, acc2[2*j+1]);
            }
        }
    }

#pragma unroll
    for (int i = 0; i < COUT / 2; i++) {
        float lo, hi;
        unpack2(acc2[i], lo, hi);
        atomicAdd(out + (2*i+0) * PP + p, lo);   // REDG: no return needed
        atomicAdd(out + (2*i+1) * PP + p, hi);
    }
}

// ---------------------------------------------------------------------------
extern "C" void kernel_launch(void* const* d_in, const int* in_sizes, int n_in,
                              void* d_out, int out_size) {
    const float* x    = (const float*)d_in[0];  // [32,16,56,56]
    const float* offw = (const float*)d_in[1];  // [81,32,3,3,3]
    const float* offb = (const float*)d_in[2];  // [81]
    const float* w    = (const float*)d_in[3];  // [64,32,3,3,3]
    const float* b    = (const float*)d_in[4];  // [64]
    float* out = (float*)d_out;                 // [64,16,56,56]

    init_kernel<<<(COUT * PP + 255) / 256, 256>>>(offw, w, b, out);
    offconv_kernel<<<392, 128>>>(x, offb);
    dim3 dgrid(DD * NYG, NCIG);                 // 224 x 4
    deform_kernel<<<dgrid, TB>>>(x, out);
}